// round 13
// baseline (speedup 1.0000x reference)
#include <cuda_runtime.h>
#include <cuda_bf16.h>

#define N_NODES 50000
#define E_EDGES 600000
#define FDIM    128
#define HDIM    16
#define OCC     4
#define NBLK    (148 * OCC)      // 592 — exactly wave-1 co-resident at occ 4
#define NTHR    256
#define GSTRIDE (NBLK * NTHR)

// device state (referenced ONLY in device code).
// g_deg/g_acc1/g_acc2 are 0 at rest; consumer phases reset them (replay-safe).
__device__ float             g_deg [N_NODES];
__device__ float             g_dinv[N_NODES];
__device__ float             g_h   [N_NODES * HDIM];   // h1s then z1s
__device__ float             g_acc1[N_NODES * HDIM];
__device__ float             g_acc2[N_NODES * HDIM];
__device__ int2              g_edges[E_EDGES];          // decoded (r,c), sentinel r=-1
__device__ unsigned          g_bar_count;               // 0 at rest
__device__ volatile unsigned g_bar_gen;                 // monotonic

__device__ __forceinline__ int load_edge_idx(const unsigned int* __restrict__ ei,
                                             int mode, int pos) {
    if (mode == 1) return (int)ei[2 * pos];             // int64: low word
    unsigned int v = ei[pos];
    if (mode == 2) return (int)__int_as_float((int)v);  // float32-encoded
    return (int)v;                                      // int32
}

__device__ __forceinline__ void red_add_f4(float* addr, float4 v) {
    asm volatile("red.global.add.v4.f32 [%0], {%1,%2,%3,%4};"
                 :: "l"(addr), "f"(v.x), "f"(v.y), "f"(v.z), "f"(v.w) : "memory");
}

// sense-reversing grid barrier (all NBLK blocks co-resident by construction)
__device__ __forceinline__ void grid_barrier() {
    __syncthreads();
    if (threadIdx.x == 0) {
        __threadfence();
        unsigned gen = g_bar_gen;
        if (atomicAdd(&g_bar_count, 1u) == NBLK - 1) {
            g_bar_count = 0;
            __threadfence();
            g_bar_gen = gen + 1u;
        } else {
            while (g_bar_gen == gen) { }
        }
        __threadfence();
    }
    __syncthreads();
}

__global__ void __launch_bounds__(NTHR, OCC)
gcn_kernel(const float* __restrict__ x, const unsigned int* __restrict__ ei,
           const float* __restrict__ W1, const float* __restrict__ b1,
           const float* __restrict__ W2, const float* __restrict__ b2,
           float* __restrict__ out) {
    __shared__ float sw[FDIM * HDIM + FDIM];   // W1, later W2|b2 (8.7 KB)
    const int tid  = threadIdx.x;
    const int gid0 = blockIdx.x * NTHR + tid;

    // ---- phase 0 (per-block): detect edge dtype ----
    int mode;
    {
        __shared__ int s_big, s_odd;
        if (tid == 0) { s_big = 0; s_odd = 0; }
        __syncthreads();
        int big = 0, odd = 0;
        for (int k = tid; k < 4096; k += NTHR) {
            unsigned int v = ei[k];
            if (v >= 0x30000000u) big++;
            if ((k & 1) && v != 0u) odd++;
        }
#pragma unroll
        for (int o = 16; o; o >>= 1) {
            big += __shfl_xor_sync(0xFFFFFFFFu, big, o);
            odd += __shfl_xor_sync(0xFFFFFFFFu, odd, o);
        }
        if ((tid & 31) == 0) {
            if (big) atomicAdd(&s_big, big);
            if (odd) atomicAdd(&s_odd, odd);
        }
        __syncthreads();
        mode = (s_big > 1024) ? 2 : ((s_odd == 0) ? 1 : 0);
    }

    // ---- phase 1: decode edges + degree count ----
    for (int e = gid0; e < E_EDGES; e += GSTRIDE) {
        int r = load_edge_idx(ei, mode, e);
        int c = load_edge_idx(ei, mode, E_EDGES + e);
        bool ok = (unsigned)r < (unsigned)N_NODES && (unsigned)c < (unsigned)N_NODES;
        g_edges[e] = make_int2(ok ? r : -1, ok ? c : 0);
        if (ok) atomicAdd(&g_deg[c], 1.0f);
    }
    grid_barrier();   // 1

    // ---- phase 2: h1s = dinv*(x@W1); publish dinv; reset deg ----
    for (int i = tid; i < FDIM * HDIM; i += NTHR) sw[i] = W1[i];
    __syncthreads();
    for (int g = gid0; g < N_NODES * 4; g += GSTRIDE) {
        int row = g >> 2;
        int jg  = (g & 3) * 4;
        float dinv = rsqrtf(g_deg[row] + 1.0f);   // +1 = self-loop

        const float4* xr = (const float4*)(x + (size_t)row * FDIM);
        float4 acc = make_float4(0.f, 0.f, 0.f, 0.f);
#pragma unroll 8
        for (int k4 = 0; k4 < FDIM / 4; k4++) {
            float4 xv = xr[k4];
            float4 w0 = *(const float4*)&sw[(k4 * 4 + 0) * HDIM + jg];
            float4 w1 = *(const float4*)&sw[(k4 * 4 + 1) * HDIM + jg];
            float4 w2 = *(const float4*)&sw[(k4 * 4 + 2) * HDIM + jg];
            float4 w3 = *(const float4*)&sw[(k4 * 4 + 3) * HDIM + jg];
            acc.x += xv.x * w0.x + xv.y * w1.x + xv.z * w2.x + xv.w * w3.x;
            acc.y += xv.x * w0.y + xv.y * w1.y + xv.z * w2.y + xv.w * w3.y;
            acc.z += xv.x * w0.z + xv.y * w1.z + xv.z * w2.z + xv.w * w3.z;
            acc.w += xv.x * w0.w + xv.y * w1.w + xv.z * w2.w + xv.w * w3.w;
        }
        acc.x *= dinv; acc.y *= dinv; acc.z *= dinv; acc.w *= dinv;
        *(float4*)(g_h + row * HDIM + jg) = acc;
        if (jg == 0) {
            g_dinv[row] = dinv;
            g_deg[row]  = 0.0f;   // self-clean (readers are in this same warp iteration)
        }
    }
    grid_barrier();   // 2

    // ---- phase 3: layer-1 scatter: acc1[c] += h1s[r] ----
    for (int e = gid0; e < E_EDGES; e += GSTRIDE) {
        int2 rc = g_edges[e];
        if (rc.x >= 0) {
            const float4* hr = (const float4*)(g_h + rc.x * HDIM);
            float*        ac = g_acc1 + rc.y * HDIM;
#pragma unroll
            for (int p = 0; p < HDIM / 4; p++)
                red_add_f4(ac + p * 4, hr[p]);
        }
    }
    grid_barrier();   // 3

    // ---- phase 4: z1s = dinv*relu(dinv*(acc1+h1s)+b1); reset acc1 (float4) ----
    {
        float4 bb[4];
#pragma unroll
        for (int p = 0; p < 4; p++) bb[p] = ((const float4*)b1)[p];
        const float4 zero4 = make_float4(0.f, 0.f, 0.f, 0.f);
        for (int g = gid0; g < N_NODES * 4; g += GSTRIDE) {
            int node = g >> 2, p = g & 3;
            float dinv = g_dinv[node];
            float4 av = ((float4*)(g_acc1 + node * HDIM))[p];
            float4 hv = ((float4*)(g_h    + node * HDIM))[p];
            float4 z;
            z.x = fmaxf(dinv * (av.x + hv.x) + bb[p].x, 0.0f) * dinv;
            z.y = fmaxf(dinv * (av.y + hv.y) + bb[p].y, 0.0f) * dinv;
            z.z = fmaxf(dinv * (av.z + hv.z) + bb[p].z, 0.0f) * dinv;
            z.w = fmaxf(dinv * (av.w + hv.w) + bb[p].w, 0.0f) * dinv;
            ((float4*)(g_h    + node * HDIM))[p] = z;
            ((float4*)(g_acc1 + node * HDIM))[p] = zero4;
        }
    }
    grid_barrier();   // 4

    // ---- phase 5: layer-2 scatter: acc2[c] += z1s[r] ----
    for (int e = gid0; e < E_EDGES; e += GSTRIDE) {
        int2 rc = g_edges[e];
        if (rc.x >= 0) {
            const float4* hr = (const float4*)(g_h + rc.x * HDIM);
            float*        ac = g_acc2 + rc.y * HDIM;
#pragma unroll
            for (int p = 0; p < HDIM / 4; p++)
                red_add_f4(ac + p * 4, hr[p]);
        }
    }
    grid_barrier();   // 5

    // ---- phase 6: out = log_softmax(dinv*(acc2+z1s) @ W2 + b2); reset acc2 ----
    for (int i = tid; i < FDIM * HDIM; i += NTHR) sw[i] = W2[i];
    for (int i = tid; i < FDIM; i += NTHR)        sw[FDIM * HDIM + i] = b2[i];
    __syncthreads();

    const int warp0  = blockIdx.x * (NTHR / 32) + (tid >> 5);
    const int lane   = tid & 31;
    const int nwarps = NBLK * (NTHR / 32);

    for (int node = warp0; node < N_NODES; node += nwarps) {
        float dinv = g_dinv[node];
        const float* ar = g_acc2 + node * HDIM;
        const float* zr = g_h    + node * HDIM;
        float a[HDIM];
#pragma unroll
        for (int k = 0; k < HDIM; k++)
            a[k] = dinv * (ar[k] + zr[k]);

        if (lane < 4)
            *(float4*)(g_acc2 + node * HDIM + lane * 4) = make_float4(0.f, 0.f, 0.f, 0.f);

        int c0 = lane * 4;
        float o0 = sw[FDIM * HDIM + c0 + 0], o1 = sw[FDIM * HDIM + c0 + 1];
        float o2 = sw[FDIM * HDIM + c0 + 2], o3 = sw[FDIM * HDIM + c0 + 3];
#pragma unroll
        for (int k = 0; k < HDIM; k++) {
            float4 w = *(const float4*)&sw[k * FDIM + c0];
            o0 += a[k] * w.x; o1 += a[k] * w.y; o2 += a[k] * w.z; o3 += a[k] * w.w;
        }

        float m = fmaxf(fmaxf(o0, o1), fmaxf(o2, o3));
#pragma unroll
        for (int off = 16; off > 0; off >>= 1)
            m = fmaxf(m, __shfl_xor_sync(0xFFFFFFFFu, m, off));

        float s = expf(o0 - m) + expf(o1 - m) + expf(o2 - m) + expf(o3 - m);
#pragma unroll
        for (int off = 16; off > 0; off >>= 1)
            s += __shfl_xor_sync(0xFFFFFFFFu, s, off);
        float lse = m + logf(s);

        float4 r = make_float4(o0 - lse, o1 - lse, o2 - lse, o3 - lse);
        *(float4*)(out + (size_t)node * FDIM + c0) = r;
    }
}

extern "C" void kernel_launch(void* const* d_in, const int* in_sizes, int n_in,
                              void* d_out, int out_size) {
    const float*        x  = nullptr;
    const unsigned int* ei = nullptr;
    const float*        W1 = nullptr;
    const float*        W2 = nullptr;
    const float*        b1 = nullptr;
    const float*        b2 = nullptr;

    for (int i = 0; i < n_in; i++) {
        long long sz = in_sizes[i];
        if (sz == 6400000LL || sz == 25600000LL)        x  = (const float*)d_in[i];
        else if (sz == 1200000LL || sz == 2400000LL ||
                 sz == 4800000LL || sz == 9600000LL)     ei = (const unsigned int*)d_in[i];
        else if (sz == 2048LL || sz == 8192LL) { if (!W1) W1 = (const float*)d_in[i];
                                                 else     W2 = (const float*)d_in[i]; }
        else if (sz == 16LL  || sz == 64LL)              b1 = (const float*)d_in[i];
        else if (sz == 128LL || sz == 512LL)             b2 = (const float*)d_in[i];
    }
    if (!x)  x  = (const float*)d_in[0];
    if (!ei) ei = (const unsigned int*)d_in[1];
    if (!W1) W1 = (const float*)d_in[2];
    if (!b1) b1 = (const float*)d_in[3];
    if (!W2) W2 = (const float*)d_in[4];
    if (!b2) b2 = (const float*)d_in[5];

    gcn_kernel<<<NBLK, NTHR>>>(x, ei, W1, b1, W2, b2, (float*)d_out);
}

// round 14
// speedup vs baseline: 1.5440x; 1.5440x over previous
#include <cuda_runtime.h>
#include <cuda_bf16.h>

#define N_NODES 50000
#define E_EDGES 600000
#define FDIM    128
#define HDIM    16

// device state — referenced ONLY inside device code.
// Self-cleaning invariant: consumer phases reset what they consume (replay-safe).
__device__ int          g_mode;
__device__ float        g_deg  [N_NODES];        // 0 at rest
__device__ float        g_dinv [N_NODES];
__device__ unsigned int g_hb   [N_NODES * 8];    // bf16x2-packed h1s, then z1s (16 feats)
__device__ unsigned int g_acc1b[N_NODES * 8];    // bf16x2 accum, 0 at rest
__device__ unsigned int g_acc2b[N_NODES * 8];    // bf16x2 accum, 0 at rest

__device__ __forceinline__ int load_edge_idx(const unsigned int* __restrict__ ei,
                                             int mode, int pos) {
    if (mode == 1) return (int)ei[2 * pos];             // int64: low word
    unsigned int v = ei[pos];
    if (mode == 2) return (int)__int_as_float((int)v);  // float32-encoded
    return (int)v;                                      // int32
}

__device__ __forceinline__ unsigned int pack_bf2(float lo, float hi) {
    __nv_bfloat162 t = __floats2bfloat162_rn(lo, hi);   // .x = lo (low half)
    return *(unsigned int*)&t;
}
__device__ __forceinline__ float2 unpack_bf2(unsigned int v) {
    __nv_bfloat162 t = *(__nv_bfloat162*)&v;
    return make_float2(__low2float(t), __high2float(t));
}

// 8 bf16 adds in one L2 atomic op (sm_90+)
__device__ __forceinline__ void red_add_bf16x2_v4(unsigned int* addr, uint4 v) {
    asm volatile("red.global.add.noftz.v4.bf16x2 [%0], {%1,%2,%3,%4};"
                 :: "l"(addr), "r"(v.x), "r"(v.y), "r"(v.z), "r"(v.w) : "memory");
}

// ---- launch 0: detect edge dtype (1 block) ----
__global__ void detect_kernel(const unsigned int* __restrict__ w) {
    __shared__ int s_big, s_odd;
    if (threadIdx.x == 0) { s_big = 0; s_odd = 0; }
    __syncthreads();
    int big = 0, odd = 0;
    for (int k = threadIdx.x; k < 4096; k += blockDim.x) {
        unsigned int v = w[k];
        if (v >= 0x30000000u) big++;
        if ((k & 1) && v != 0u) odd++;
    }
    if (big) atomicAdd(&s_big, big);
    if (odd) atomicAdd(&s_odd, odd);
    __syncthreads();
    if (threadIdx.x == 0) {
        if (s_big > 1024)     g_mode = 2;
        else if (s_odd == 0)  g_mode = 1;
        else                  g_mode = 0;
    }
}

// ---- launch 1: degree count over targets (g_deg 0 at rest) ----
__global__ void deg_kernel(const unsigned int* __restrict__ ei) {
    int e = blockIdx.x * blockDim.x + threadIdx.x;
    if (e < E_EDGES) {
        int c = load_edge_idx(ei, g_mode, E_EDGES + e);
        if ((unsigned)c < (unsigned)N_NODES)
            atomicAdd(&g_deg[c], 1.0f);
    }
}

// ---- launch 2: h1s = dinv*(x@W1), bf16x2-packed; publish dinv; reset deg ----
// 4 threads per row, 4 output features each.
__global__ void gemm1_kernel(const float* __restrict__ x, const float* __restrict__ W1) {
    __shared__ float sW1[FDIM * HDIM];
    for (int i = threadIdx.x; i < FDIM * HDIM; i += blockDim.x)
        sW1[i] = W1[i];
    __syncthreads();

    int gid = blockIdx.x * blockDim.x + threadIdx.x;
    int row = gid >> 2;
    int q   = gid & 3;
    int jg  = q * 4;
    if (row >= N_NODES) return;

    float dinv = rsqrtf(g_deg[row] + 1.0f);   // +1 = self-loop

    const float4* xr = (const float4*)(x + (size_t)row * FDIM);
    float4 acc = make_float4(0.f, 0.f, 0.f, 0.f);
#pragma unroll
    for (int k4 = 0; k4 < FDIM / 4; k4++) {
        float4 xv = xr[k4];
        float4 w0 = *(const float4*)&sW1[(k4 * 4 + 0) * HDIM + jg];
        float4 w1 = *(const float4*)&sW1[(k4 * 4 + 1) * HDIM + jg];
        float4 w2 = *(const float4*)&sW1[(k4 * 4 + 2) * HDIM + jg];
        float4 w3 = *(const float4*)&sW1[(k4 * 4 + 3) * HDIM + jg];
        acc.x += xv.x * w0.x + xv.y * w1.x + xv.z * w2.x + xv.w * w3.x;
        acc.y += xv.x * w0.y + xv.y * w1.y + xv.z * w2.y + xv.w * w3.y;
        acc.z += xv.x * w0.z + xv.y * w1.z + xv.z * w2.z + xv.w * w3.z;
        acc.w += xv.x * w0.w + xv.y * w1.w + xv.z * w2.w + xv.w * w3.w;
    }
    uint2 packed;
    packed.x = pack_bf2(acc.x * dinv, acc.y * dinv);
    packed.y = pack_bf2(acc.z * dinv, acc.w * dinv);
    *(uint2*)(g_hb + row * 8 + q * 2) = packed;

    if (q == 0) {
        g_dinv[row] = dinv;
        g_deg[row]  = 0.0f;    // self-clean for next replay
    }
}

// ---- launches 3 & 5: gather 32B + two v4.bf16x2 REDs per edge ----
template <int PASS>
__global__ void agg_kernel(const unsigned int* __restrict__ ei) {
    int e = blockIdx.x * blockDim.x + threadIdx.x;
    if (e >= E_EDGES) return;

    unsigned int* __restrict__ acc = (PASS == 0) ? g_acc1b : g_acc2b;

    int mode = g_mode;
    int r = load_edge_idx(ei, mode, e);
    int c = load_edge_idx(ei, mode, E_EDGES + e);
    if ((unsigned)r >= (unsigned)N_NODES || (unsigned)c >= (unsigned)N_NODES) return;

    const uint4* hr = (const uint4*)(g_hb + r * 8);
    uint4 lo = hr[0];
    uint4 hi = hr[1];
    unsigned int* ac = acc + c * 8;
    red_add_bf16x2_v4(ac,     lo);
    red_add_bf16x2_v4(ac + 4, hi);
}

// ---- launch 4: z1s = dinv*relu(dinv*(acc1+h1s)+b1) (bf16x2); reset acc1 ----
__global__ void relu_bias_kernel(const float* __restrict__ b1) {
    int idx = blockIdx.x * blockDim.x + threadIdx.x;   // over N_NODES*8 u32 words
    if (idx >= N_NODES * 8) return;
    int node = idx >> 3;
    int j0   = (idx & 7) * 2;
    float dinv = g_dinv[node];
    float2 av = unpack_bf2(g_acc1b[idx]);
    float2 hv = unpack_bf2(g_hb[idx]);
    float z0 = fmaxf(dinv * (av.x + hv.x) + b1[j0 + 0], 0.0f) * dinv;
    float z1 = fmaxf(dinv * (av.y + hv.y) + b1[j0 + 1], 0.0f) * dinv;
    g_hb[idx]    = pack_bf2(z0, z1);
    g_acc1b[idx] = 0u;          // self-clean
}

// ---- launch 6: out = log_softmax(dinv*(acc2+z1s) @ W2 + b2); reset acc2 ----
__global__ void final_kernel(const float* __restrict__ W2, const float* __restrict__ b2,
                             float* __restrict__ out) {
    __shared__ float sW2[HDIM * FDIM];
    __shared__ float sb2[FDIM];
    for (int i = threadIdx.x; i < HDIM * FDIM; i += blockDim.x) sW2[i] = W2[i];
    for (int i = threadIdx.x; i < FDIM; i += blockDim.x)        sb2[i] = b2[i];
    __syncthreads();

    int warp = (blockIdx.x * blockDim.x + threadIdx.x) >> 5;
    int lane = threadIdx.x & 31;
    if (warp >= N_NODES) return;

    float dinv = g_dinv[warp];
    float a[HDIM];
#pragma unroll
    for (int t = 0; t < 8; t++) {                 // broadcast loads within warp
        float2 av = unpack_bf2(g_acc2b[warp * 8 + t]);
        float2 hv = unpack_bf2(g_hb   [warp * 8 + t]);
        a[2 * t + 0] = dinv * (av.x + hv.x);
        a[2 * t + 1] = dinv * (av.y + hv.y);
    }
    if (lane < 2)                                  // self-clean acc2 (2 x 16B)
        *(uint4*)(g_acc2b + warp * 8 + lane * 4) = make_uint4(0u, 0u, 0u, 0u);

    int c0 = lane * 4;
    float o0 = sb2[c0 + 0], o1 = sb2[c0 + 1], o2 = sb2[c0 + 2], o3 = sb2[c0 + 3];
#pragma unroll
    for (int k = 0; k < HDIM; k++) {
        float4 w = *(const float4*)&sW2[k * FDIM + c0];
        o0 += a[k] * w.x; o1 += a[k] * w.y; o2 += a[k] * w.z; o3 += a[k] * w.w;
    }

    float m = fmaxf(fmaxf(o0, o1), fmaxf(o2, o3));
#pragma unroll
    for (int off = 16; off > 0; off >>= 1)
        m = fmaxf(m, __shfl_xor_sync(0xFFFFFFFFu, m, off));

    float s = expf(o0 - m) + expf(o1 - m) + expf(o2 - m) + expf(o3 - m);
#pragma unroll
    for (int off = 16; off > 0; off >>= 1)
        s += __shfl_xor_sync(0xFFFFFFFFu, s, off);
    float lse = m + logf(s);

    float4 r = make_float4(o0 - lse, o1 - lse, o2 - lse, o3 - lse);
    *(float4*)(out + (size_t)warp * FDIM + c0) = r;
}

extern "C" void kernel_launch(void* const* d_in, const int* in_sizes, int n_in,
                              void* d_out, int out_size) {
    const float*        x  = nullptr;
    const unsigned int* ei = nullptr;
    const float*        W1 = nullptr;
    const float*        W2 = nullptr;
    const float*        b1 = nullptr;
    const float*        b2 = nullptr;

    for (int i = 0; i < n_in; i++) {
        long long sz = in_sizes[i];
        if (sz == 6400000LL || sz == 25600000LL)        x  = (const float*)d_in[i];
        else if (sz == 1200000LL || sz == 2400000LL ||
                 sz == 4800000LL || sz == 9600000LL)     ei = (const unsigned int*)d_in[i];
        else if (sz == 2048LL || sz == 8192LL) { if (!W1) W1 = (const float*)d_in[i];
                                                 else     W2 = (const float*)d_in[i]; }
        else if (sz == 16LL  || sz == 64LL)              b1 = (const float*)d_in[i];
        else if (sz == 128LL || sz == 512LL)             b2 = (const float*)d_in[i];
    }
    if (!x)  x  = (const float*)d_in[0];
    if (!ei) ei = (const unsigned int*)d_in[1];
    if (!W1) W1 = (const float*)d_in[2];
    if (!b1) b1 = (const float*)d_in[3];
    if (!W2) W2 = (const float*)d_in[4];
    if (!b2) b2 = (const float*)d_in[5];

    float* out = (float*)d_out;
    const int T = 256;

    detect_kernel<<<1, T>>>(ei);                                    // 0
    deg_kernel<<<(E_EDGES + T - 1) / T, T>>>(ei);                   // 1
    gemm1_kernel<<<(N_NODES * 4 + T - 1) / T, T>>>(x, W1);          // 2
    agg_kernel<0><<<(E_EDGES + T - 1) / T, T>>>(ei);                // 3
    relu_bias_kernel<<<(N_NODES * 8 + T - 1) / T, T>>>(b1);         // 4
    agg_kernel<1><<<(E_EDGES + T - 1) / T, T>>>(ei);                // 5  <- ncu -s 5
    final_kernel<<<(N_NODES * 32 + T - 1) / T, T>>>(W2, b2, out);   // 6
}

// round 15
// speedup vs baseline: 1.5853x; 1.0268x over previous
#include <cuda_runtime.h>
#include <cuda_bf16.h>

#define N_NODES 50000
#define E_EDGES 600000
#define EHALF   (E_EDGES / 2)
#define FDIM    128
#define HDIM    16

// device state — referenced ONLY inside device code.
// Self-cleaning invariant: consumer phases reset what they consume (replay-safe).
__device__ int          g_mode;
__device__ float        g_deg  [N_NODES];        // 0 at rest
__device__ float        g_dinv [N_NODES];
__device__ unsigned int g_hb   [N_NODES * 8];    // bf16x2-packed h1s, then z1s
__device__ unsigned int g_acc1b[N_NODES * 8];    // bf16x2 accum, 0 at rest
__device__ unsigned int g_acc2b[N_NODES * 8];    // bf16x2 accum, 0 at rest

__device__ __forceinline__ int load_edge_idx(const unsigned int* __restrict__ ei,
                                             int mode, int pos) {
    if (mode == 1) return (int)ei[2 * pos];             // int64: low word
    unsigned int v = ei[pos];
    if (mode == 2) return (int)__int_as_float((int)v);  // float32-encoded
    return (int)v;                                      // int32
}

__device__ __forceinline__ unsigned int pack_bf2(float lo, float hi) {
    __nv_bfloat162 t = __floats2bfloat162_rn(lo, hi);
    return *(unsigned int*)&t;
}
__device__ __forceinline__ float2 unpack_bf2(unsigned int v) {
    __nv_bfloat162 t = *(__nv_bfloat162*)&v;
    return make_float2(__low2float(t), __high2float(t));
}

// 8 bf16 adds in one L2 atomic op (sm_90+)
__device__ __forceinline__ void red_add_bf16x2_v4(unsigned int* addr, uint4 v) {
    asm volatile("red.global.add.noftz.v4.bf16x2 [%0], {%1,%2,%3,%4};"
                 :: "l"(addr), "r"(v.x), "r"(v.y), "r"(v.z), "r"(v.w) : "memory");
}

// per-block edge-dtype sniff from the first 256 words (1 KB)
__device__ __forceinline__ int detect_mode_block(const unsigned int* __restrict__ ei) {
    __shared__ int s_big, s_odd;
    if (threadIdx.x == 0) { s_big = 0; s_odd = 0; }
    __syncthreads();
    if (threadIdx.x < 256) {
        unsigned int v = ei[threadIdx.x];
        if (v >= 0x30000000u)              atomicAdd(&s_big, 1);
        if ((threadIdx.x & 1) && v != 0u)  atomicAdd(&s_odd, 1);
    }
    __syncthreads();
    return (s_big > 64) ? 2 : ((s_odd == 0) ? 1 : 0);
}

// ---- launch 0: detect (per block) + degree count over targets ----
__global__ void deg_kernel(const unsigned int* __restrict__ ei) {
    int mode = detect_mode_block(ei);
    if (blockIdx.x == 0 && threadIdx.x == 0)
        g_mode = mode;                      // published for later launches

    int e = blockIdx.x * blockDim.x + threadIdx.x;
    if (e < E_EDGES) {
        int c = load_edge_idx(ei, mode, E_EDGES + e);
        if ((unsigned)c < (unsigned)N_NODES)
            atomicAdd(&g_deg[c], 1.0f);
    }
}

// ---- launch 1: h1s = dinv*(x@W1), bf16x2-packed; publish dinv; reset deg ----
__global__ void gemm1_kernel(const float* __restrict__ x, const float* __restrict__ W1) {
    __shared__ float sW1[FDIM * HDIM];
    for (int i = threadIdx.x; i < FDIM * HDIM; i += blockDim.x)
        sW1[i] = W1[i];
    __syncthreads();

    int gid = blockIdx.x * blockDim.x + threadIdx.x;
    int row = gid >> 2;
    int q   = gid & 3;
    int jg  = q * 4;
    if (row >= N_NODES) return;

    float dinv = rsqrtf(g_deg[row] + 1.0f);   // +1 = self-loop

    const float4* xr = (const float4*)(x + (size_t)row * FDIM);
    float4 acc = make_float4(0.f, 0.f, 0.f, 0.f);
#pragma unroll
    for (int k4 = 0; k4 < FDIM / 4; k4++) {
        float4 xv = xr[k4];
        float4 w0 = *(const float4*)&sW1[(k4 * 4 + 0) * HDIM + jg];
        float4 w1 = *(const float4*)&sW1[(k4 * 4 + 1) * HDIM + jg];
        float4 w2 = *(const float4*)&sW1[(k4 * 4 + 2) * HDIM + jg];
        float4 w3 = *(const float4*)&sW1[(k4 * 4 + 3) * HDIM + jg];
        acc.x += xv.x * w0.x + xv.y * w1.x + xv.z * w2.x + xv.w * w3.x;
        acc.y += xv.x * w0.y + xv.y * w1.y + xv.z * w2.y + xv.w * w3.y;
        acc.z += xv.x * w0.z + xv.y * w1.z + xv.z * w2.z + xv.w * w3.z;
        acc.w += xv.x * w0.w + xv.y * w1.w + xv.z * w2.w + xv.w * w3.w;
    }
    uint2 packed;
    packed.x = pack_bf2(acc.x * dinv, acc.y * dinv);
    packed.y = pack_bf2(acc.z * dinv, acc.w * dinv);
    *(uint2*)(g_hb + row * 8 + q * 2) = packed;

    if (q == 0) {
        g_dinv[row] = dinv;
        g_deg[row]  = 0.0f;    // self-clean for next replay
    }
}

// ---- launches 2 & 4: aggregation, 2 edges/thread for MLP ----
template <int PASS>
__global__ void agg_kernel(const unsigned int* __restrict__ ei) {
    int e0 = blockIdx.x * blockDim.x + threadIdx.x;
    if (e0 >= EHALF) return;
    int e1 = e0 + EHALF;

    unsigned int* __restrict__ acc = (PASS == 0) ? g_acc1b : g_acc2b;
    int mode = g_mode;

    // issue both index pairs up front (independent loads)
    int r0 = load_edge_idx(ei, mode, e0);
    int c0 = load_edge_idx(ei, mode, E_EDGES + e0);
    int r1 = load_edge_idx(ei, mode, e1);
    int c1 = load_edge_idx(ei, mode, E_EDGES + e1);

    bool ok0 = (unsigned)r0 < (unsigned)N_NODES && (unsigned)c0 < (unsigned)N_NODES;
    bool ok1 = (unsigned)r1 < (unsigned)N_NODES && (unsigned)c1 < (unsigned)N_NODES;

    // issue both gathers before any RED (independent loads)
    uint4 lo0, hi0, lo1, hi1;
    if (ok0) {
        const uint4* h0 = (const uint4*)(g_hb + r0 * 8);
        lo0 = h0[0]; hi0 = h0[1];
    }
    if (ok1) {
        const uint4* h1 = (const uint4*)(g_hb + r1 * 8);
        lo1 = h1[0]; hi1 = h1[1];
    }
    if (ok0) {
        unsigned int* ac = acc + c0 * 8;
        red_add_bf16x2_v4(ac,     lo0);
        red_add_bf16x2_v4(ac + 4, hi0);
    }
    if (ok1) {
        unsigned int* ac = acc + c1 * 8;
        red_add_bf16x2_v4(ac,     lo1);
        red_add_bf16x2_v4(ac + 4, hi1);
    }
}

// ---- launch 3: z1s = dinv*relu(dinv*(acc1+h1s)+b1) (bf16x2); reset acc1 ----
__global__ void relu_bias_kernel(const float* __restrict__ b1) {
    int idx = blockIdx.x * blockDim.x + threadIdx.x;   // N_NODES*8 u32 words
    if (idx >= N_NODES * 8) return;
    int node = idx >> 3;
    int j0   = (idx & 7) * 2;
    float dinv = g_dinv[node];
    float2 av = unpack_bf2(g_acc1b[idx]);
    float2 hv = unpack_bf2(g_hb[idx]);
    float z0 = fmaxf(dinv * (av.x + hv.x) + b1[j0 + 0], 0.0f) * dinv;
    float z1 = fmaxf(dinv * (av.y + hv.y) + b1[j0 + 1], 0.0f) * dinv;
    g_hb[idx]    = pack_bf2(z0, z1);
    g_acc1b[idx] = 0u;          // self-clean
}

// ---- launch 5: out = log_softmax(dinv*(acc2+z1s) @ W2 + b2); reset acc2 ----
__global__ void final_kernel(const float* __restrict__ W2, const float* __restrict__ b2,
                             float* __restrict__ out) {
    __shared__ float sW2[HDIM * FDIM];
    __shared__ float sb2[FDIM];
    for (int i = threadIdx.x; i < HDIM * FDIM; i += blockDim.x) sW2[i] = W2[i];
    for (int i = threadIdx.x; i < FDIM; i += blockDim.x)        sb2[i] = b2[i];
    __syncthreads();

    int warp = (blockIdx.x * blockDim.x + threadIdx.x) >> 5;
    int lane = threadIdx.x & 31;
    if (warp >= N_NODES) return;

    float dinv = g_dinv[warp];
    float a[HDIM];
#pragma unroll
    for (int t = 0; t < 8; t++) {
        float2 av = unpack_bf2(g_acc2b[warp * 8 + t]);
        float2 hv = unpack_bf2(g_hb   [warp * 8 + t]);
        a[2 * t + 0] = dinv * (av.x + hv.x);
        a[2 * t + 1] = dinv * (av.y + hv.y);
    }
    if (lane < 2)
        *(uint4*)(g_acc2b + warp * 8 + lane * 4) = make_uint4(0u, 0u, 0u, 0u);

    int c0 = lane * 4;
    float o0 = sb2[c0 + 0], o1 = sb2[c0 + 1], o2 = sb2[c0 + 2], o3 = sb2[c0 + 3];
#pragma unroll
    for (int k = 0; k < HDIM; k++) {
        float4 w = *(const float4*)&sW2[k * FDIM + c0];
        o0 += a[k] * w.x; o1 += a[k] * w.y; o2 += a[k] * w.z; o3 += a[k] * w.w;
    }

    float m = fmaxf(fmaxf(o0, o1), fmaxf(o2, o3));
#pragma unroll
    for (int off = 16; off > 0; off >>= 1)
        m = fmaxf(m, __shfl_xor_sync(0xFFFFFFFFu, m, off));

    float s = expf(o0 - m) + expf(o1 - m) + expf(o2 - m) + expf(o3 - m);
#pragma unroll
    for (int off = 16; off > 0; off >>= 1)
        s += __shfl_xor_sync(0xFFFFFFFFu, s, off);
    float lse = m + logf(s);

    float4 r = make_float4(o0 - lse, o1 - lse, o2 - lse, o3 - lse);
    *(float4*)(out + (size_t)warp * FDIM + c0) = r;
}

extern "C" void kernel_launch(void* const* d_in, const int* in_sizes, int n_in,
                              void* d_out, int out_size) {
    const float*        x  = nullptr;
    const unsigned int* ei = nullptr;
    const float*        W1 = nullptr;
    const float*        W2 = nullptr;
    const float*        b1 = nullptr;
    const float*        b2 = nullptr;

    for (int i = 0; i < n_in; i++) {
        long long sz = in_sizes[i];
        if (sz == 6400000LL || sz == 25600000LL)        x  = (const float*)d_in[i];
        else if (sz == 1200000LL || sz == 2400000LL ||
                 sz == 4800000LL || sz == 9600000LL)     ei = (const unsigned int*)d_in[i];
        else if (sz == 2048LL || sz == 8192LL) { if (!W1) W1 = (const float*)d_in[i];
                                                 else     W2 = (const float*)d_in[i]; }
        else if (sz == 16LL  || sz == 64LL)              b1 = (const float*)d_in[i];
        else if (sz == 128LL || sz == 512LL)             b2 = (const float*)d_in[i];
    }
    if (!x)  x  = (const float*)d_in[0];
    if (!ei) ei = (const unsigned int*)d_in[1];
    if (!W1) W1 = (const float*)d_in[2];
    if (!b1) b1 = (const float*)d_in[3];
    if (!W2) W2 = (const float*)d_in[4];
    if (!b2) b2 = (const float*)d_in[5];

    float* out = (float*)d_out;
    const int T = 256;

    deg_kernel<<<(E_EDGES + T - 1) / T, T>>>(ei);                   // 0 (detect fused)
    gemm1_kernel<<<(N_NODES * 4 + T - 1) / T, T>>>(x, W1);          // 1
    agg_kernel<0><<<(EHALF + T - 1) / T, T>>>(ei);                  // 2
    relu_bias_kernel<<<(N_NODES * 8 + T - 1) / T, T>>>(b1);         // 3
    agg_kernel<1><<<(EHALF + T - 1) / T, T>>>(ei);                  // 4
    final_kernel<<<(N_NODES * 32 + T - 1) / T, T>>>(W2, b2, out);   // 5  <- ncu -s 5
}